// round 4
// baseline (speedup 1.0000x reference)
#include <cuda_runtime.h>

#define RES 4096
#define NQ  (RES / 4)
#define NTOT (RES * RES)
#define INV_AREA (1.0f / 121.0f)

// Temporal-blocked Jacobi tile params
#define KF 4                 // fused steps per pass
#define RX 128               // region cols (32 float4)
#define RY 64                // region rows
#define TX 120               // valid output cols
#define TY 56                // valid output rows
#define NTHREADS 512
#define RPT 4                // rows per thread (RY / 16 warps)

// Box-filter tile params
#define BOX_TX 128
#define BOX_TY 32
#define BOX_H  5
#define SRC_R (BOX_TY + 2 * BOX_H)   // 42
#define SRC_C (BOX_TX + 2 * BOX_H)   // 138
#define SRC_CP 140                   // padded smem stride

// Scratch (device globals — no allocation allowed)
__device__ float g_V0[NTOT];
__device__ float g_V1[NTOT];
__device__ float g_E[NTOT];
__device__ float g_T[NTOT];

// ---------------------------------------------------------------------------
// Kernel 1: init V0, C_pos output, objects_bounds   (float4)
// ---------------------------------------------------------------------------
__global__ void k_init(const float4* __restrict__ x,
                       const float4* __restrict__ bt,
                       const float4* __restrict__ bc,
                       const float4* __restrict__ C,
                       float4* __restrict__ cpos_out) {
    int i = blockIdx.x * blockDim.x + threadIdx.x;
    if (i >= NTOT / 4) return;
    float4 btv = bt[i];
    float4 bcv = bc[i];
    float4 cv  = C[i];
    float4 xv  = x[i];
    float4 cp;
    cp.x = fmaxf(cv.x, 0.f); cp.y = fmaxf(cv.y, 0.f);
    cp.z = fmaxf(cv.z, 0.f); cp.w = fmaxf(cv.w, 0.f);
    cpos_out[i] = cp;
    float4 v0;
    v0.x = (btv.x > 0.f) ? bcv.x : xv.x;
    v0.y = (btv.y > 0.f) ? bcv.y : xv.y;
    v0.z = (btv.z > 0.f) ? bcv.z : xv.z;
    v0.w = (btv.w > 0.f) ? bcv.w : xv.w;
    ((float4*)g_V0)[i] = v0;
    float4 t;
    t.x = (btv.x == 1.f && bcv.x > 0.f) ? bcv.x : 0.f;
    t.y = (btv.y == 1.f && bcv.y > 0.f) ? bcv.y : 0.f;
    t.z = (btv.z == 1.f && bcv.z > 0.f) ? bcv.z : 0.f;
    t.w = (btv.w == 1.f && bcv.w > 0.f) ? bcv.w : 0.f;
    ((float4*)g_T)[i] = t;
}

// ---------------------------------------------------------------------------
// Kernel 2: fused 11x11 box filter (zero-pad) + encoded-E build.
// Per block: 128x32 output tile, smem staging for T and horizontal sums.
// ---------------------------------------------------------------------------
__global__ __launch_bounds__(256)
void k_box(const float* __restrict__ bt,
           const float* __restrict__ bc,
           const float* __restrict__ cpos) {
    __shared__ float sT[SRC_R * SRC_CP];   // 42*140*4 = 23.0 KB
    __shared__ float sH[SRC_R * BOX_TX];   // 42*128*4 = 21.0 KB
    int tid  = threadIdx.x;
    int lane = tid & 31;
    int w    = tid >> 5;                   // 8 warps
    int gr0 = blockIdx.y * BOX_TY;
    int gc0 = blockIdx.x * BOX_TX;

    // load T region with zero pad
    for (int r = w; r < SRC_R; r += 8) {
        int gr = gr0 - BOX_H + r;
        for (int c = lane; c < SRC_C; c += 32) {
            int gc = gc0 - BOX_H + c;
            float v = 0.f;
            if (gr >= 0 && gr < RES && gc >= 0 && gc < RES)
                v = __ldg(g_T + (size_t)gr * RES + gc);
            sT[r * SRC_CP + c] = v;
        }
    }
    __syncthreads();

    // horizontal 11-wide sum
    for (int r = w; r < SRC_R; r += 8) {
        for (int c = lane; c < BOX_TX; c += 32) {
            float s = 0.f;
            #pragma unroll
            for (int d = 0; d < 11; d++) s += sT[r * SRC_CP + c + d];
            sH[r * BOX_TX + c] = s;
        }
    }
    __syncthreads();

    // vertical 11-wide sum + combine -> E
    for (int rr = w; rr < BOX_TY; rr += 8) {
        int gr = gr0 + rr;
        for (int cc = lane; cc < BOX_TX; cc += 32) {
            float s = 0.f;
            #pragma unroll
            for (int d = 0; d < 11; d++) s += sH[(rr + d) * BOX_TX + cc];
            size_t i = (size_t)gr * RES + (gc0 + cc);
            float btv = __ldg(bt + i);
            float ev = (btv == 0.f) ? __ldg(cpos + i) + s * INV_AREA
                                    : -__ldg(bc + i) - 1.f;
            g_E[i] = ev;
        }
    }
}

// ---------------------------------------------------------------------------
// Kernel 3: KF fused Jacobi steps, 128x64 smem tile, 512 threads.
// 16 warps x 4 rows. E in registers; vertical rolling; horiz via shfl.
// Interior tiles (no global-edge contact) take a predicate-free fast path.
// ---------------------------------------------------------------------------
__device__ __forceinline__ float4 ld4s(const float* b, int r, int tx) {
    return *(const float4*)(b + r * RX + 4 * tx);
}
__device__ __forceinline__ void st4s(float* b, int r, int tx, float4 v) {
    *(float4*)(b + r * RX + 4 * tx) = v;
}

template <bool BORDER>
__device__ __forceinline__ void jfuse_body(const float* __restrict__ Vin,
                                           float* __restrict__ Vout,
                                           int isfinal,
                                           float* sA, float* sB) {
    int tx = threadIdx.x & 31;
    int ty = threadIdx.x >> 5;            // 0..15
    int gr0 = blockIdx.y * TY - KF;
    int gc0 = blockIdx.x * TX - KF;
    int cb  = gc0 + tx * 4;
    int r0  = ty * RPT;

    bool is_ledge = BORDER && (cb == 0);
    bool is_redge = BORDER && (cb + 3 == RES - 1);

    // ---- fill: V -> sA, E -> registers ----
    float4 e[RPT];
    #pragma unroll
    for (int j = 0; j < RPT; j++) {
        int r = r0 + j;
        float4 v, ev;
        if (!BORDER) {
            size_t off = (size_t)(gr0 + r) * RES + cb;
            v  = *(const float4*)(Vin + off);
            ev = *(const float4*)(g_E + off);
        } else {
            int gr = min(max(gr0 + r, 0), RES - 1);
            size_t rowoff = (size_t)gr * RES;
            if (cb >= 0 && cb + 3 < RES) {
                v  = *(const float4*)(Vin + rowoff + cb);
                ev = *(const float4*)(g_E + rowoff + cb);
            } else {
                int c0i = min(max(cb + 0, 0), RES - 1);
                int c1i = min(max(cb + 1, 0), RES - 1);
                int c2i = min(max(cb + 2, 0), RES - 1);
                int c3i = min(max(cb + 3, 0), RES - 1);
                v  = make_float4(Vin[rowoff + c0i], Vin[rowoff + c1i],
                                 Vin[rowoff + c2i], Vin[rowoff + c3i]);
                ev = make_float4(g_E[rowoff + c0i], g_E[rowoff + c1i],
                                 g_E[rowoff + c2i], g_E[rowoff + c3i]);
            }
        }
        st4s(sA, r, tx, v);
        e[j] = ev;
    }
    __syncthreads();

    const float* bin = sA;
    float* bout = sB;

    #pragma unroll
    for (int s = 0; s < KF; s++) {
        bool last = (s == KF - 1);
        float4 cur  = ld4s(bin, r0, tx);
        float4 prev = ld4s(bin, (r0 > 0) ? r0 - 1 : 0, tx);
        #pragma unroll
        for (int j = 0; j < RPT; j++) {
            int r = r0 + j;
            float4 nxt = ld4s(bin, (r < RY - 1) ? r + 1 : r, tx);
            float4 up = prev;
            float4 dn = nxt;
            if (BORDER) {
                int grr = gr0 + r;
                if (grr <= 0)       up = cur;
                if (grr >= RES - 1) dn = cur;
            }
            float lf = __shfl_up_sync(0xffffffffu, cur.w, 1);
            float rg = __shfl_down_sync(0xffffffffu, cur.x, 1);
            if (tx == 0 || is_ledge)  lf = cur.x;
            if (tx == 31 || is_redge) rg = cur.w;
            float4 ee = e[j];
            float4 o;
            o.x = (ee.x >= 0.f) ? 0.25f * (up.x + dn.x + lf    + cur.y) + ee.x : -ee.x - 1.f;
            o.y = (ee.y >= 0.f) ? 0.25f * (up.y + dn.y + cur.x + cur.z) + ee.y : -ee.y - 1.f;
            o.z = (ee.z >= 0.f) ? 0.25f * (up.z + dn.z + cur.y + cur.w) + ee.z : -ee.z - 1.f;
            o.w = (ee.w >= 0.f) ? 0.25f * (up.w + dn.w + cur.z + rg   ) + ee.w : -ee.w - 1.f;
            if (!last) {
                st4s(bout, r, tx, o);
            } else {
                if (r >= KF && r < RY - KF && tx >= 1 && tx <= 30) {
                    bool ok = true;
                    if (BORDER) ok = (gr0 + r) < RES && (cb + 3) < RES;
                    if (ok) {
                        if (isfinal) {
                            o.x = (o.x >= 1.f) ? 0.95f : o.x;
                            o.y = (o.y >= 1.f) ? 0.95f : o.y;
                            o.z = (o.z >= 1.f) ? 0.95f : o.z;
                            o.w = (o.w >= 1.f) ? 0.95f : o.w;
                        }
                        *(float4*)(Vout + (size_t)(gr0 + r) * RES + cb) = o;
                    }
                }
            }
            prev = cur; cur = nxt;
        }
        if (!last) {
            __syncthreads();
            const float* t = bin; bin = bout; bout = (float*)t;
        }
    }
}

__global__ __launch_bounds__(NTHREADS, 2)
void k_jfuse(const float* __restrict__ Vin, float* __restrict__ Vout, int isfinal) {
    extern __shared__ float smem[];
    float* sA = smem;
    float* sB = smem + RY * RX;
    bool border = (blockIdx.x == 0) | (blockIdx.x == gridDim.x - 1) |
                  (blockIdx.y == 0) | (blockIdx.y == gridDim.y - 1);
    if (!border) jfuse_body<false>(Vin, Vout, isfinal, sA, sB);
    else         jfuse_body<true >(Vin, Vout, isfinal, sA, sB);
}

// ---------------------------------------------------------------------------
extern "C" void kernel_launch(void* const* d_in, const int* in_sizes, int n_in,
                              void* d_out, int out_size) {
    const float* x  = (const float*)d_in[0];
    const float* bt = (const float*)d_in[1];
    const float* bc = (const float*)d_in[2];
    const float* C  = (const float*)d_in[3];
    float* out  = (float*)d_out;
    float* cpos = out + (size_t)NTOT;

    // init (float4)
    {
        dim3 b(256), g((NTOT / 4 + 255) / 256);
        k_init<<<g, b>>>((const float4*)x, (const float4*)bt,
                         (const float4*)bc, (const float4*)C,
                         (float4*)cpos);
    }
    // fused 11x11 box filter + E build
    {
        dim3 b(256), g(RES / BOX_TX, RES / BOX_TY);   // 32 x 128
        k_box<<<g, b>>>(bt, bc, cpos);
    }
    // 20 Jacobi iters = 5 fused passes of KF=4
    {
        static int smem_set = 0;
        int smem_bytes = 2 * RY * RX * (int)sizeof(float);   // 64 KB
        if (!smem_set) {
            cudaFuncSetAttribute(k_jfuse,
                cudaFuncAttributeMaxDynamicSharedMemorySize, smem_bytes);
            smem_set = 1;
        }
        float *dv0, *dv1;
        cudaGetSymbolAddress((void**)&dv0, g_V0);
        cudaGetSymbolAddress((void**)&dv1, g_V1);
        dim3 b(NTHREADS), g((RES + TX - 1) / TX, (RES + TY - 1) / TY);   // 35 x 74
        k_jfuse<<<g, b, smem_bytes>>>(dv0, dv1, 0);
        k_jfuse<<<g, b, smem_bytes>>>(dv1, dv0, 0);
        k_jfuse<<<g, b, smem_bytes>>>(dv0, dv1, 0);
        k_jfuse<<<g, b, smem_bytes>>>(dv1, dv0, 0);
        k_jfuse<<<g, b, smem_bytes>>>(dv0, out, 1);   // final 4 steps + clamp
    }
}

// round 5
// speedup vs baseline: 1.2212x; 1.2212x over previous
#include <cuda_runtime.h>

#define RES 4096
#define NQ  (RES / 4)
#define NTOT (RES * RES)
#define HALF 5
#define INV_AREA (1.0f / 121.0f)

// Temporal-blocked Jacobi tile params
#define KF 4                 // fused steps per pass
#define RX 128               // region cols (32 float4)
#define RY 64                // region rows
#define TX 120               // valid output cols
#define TY 56                // valid output rows
#define NTHREADS 512
#define RPT 4                // rows per thread (RY / 16 warps)
#define NWY 16               // warps (strips) in y

// Scratch (device globals — no allocation allowed)
__device__ float g_V0[NTOT];
__device__ float g_V1[NTOT];
__device__ float g_E[NTOT];
__device__ float g_T[NTOT];

// ---------------------------------------------------------------------------
// Kernel 1: init V0, C_pos output, objects_bounds   (float4)
// ---------------------------------------------------------------------------
__global__ void k_init(const float4* __restrict__ x,
                       const float4* __restrict__ bt,
                       const float4* __restrict__ bc,
                       const float4* __restrict__ C,
                       float4* __restrict__ cpos_out) {
    int i = blockIdx.x * blockDim.x + threadIdx.x;
    if (i >= NTOT / 4) return;
    float4 btv = bt[i];
    float4 bcv = bc[i];
    float4 cv  = C[i];
    float4 xv  = x[i];
    float4 cp;
    cp.x = fmaxf(cv.x, 0.f); cp.y = fmaxf(cv.y, 0.f);
    cp.z = fmaxf(cv.z, 0.f); cp.w = fmaxf(cv.w, 0.f);
    cpos_out[i] = cp;
    float4 v0;
    v0.x = (btv.x > 0.f) ? bcv.x : xv.x;
    v0.y = (btv.y > 0.f) ? bcv.y : xv.y;
    v0.z = (btv.z > 0.f) ? bcv.z : xv.z;
    v0.w = (btv.w > 0.f) ? bcv.w : xv.w;
    ((float4*)g_V0)[i] = v0;
    float4 t;
    t.x = (btv.x == 1.f && bcv.x > 0.f) ? bcv.x : 0.f;
    t.y = (btv.y == 1.f && bcv.y > 0.f) ? bcv.y : 0.f;
    t.z = (btv.z == 1.f && bcv.z > 0.f) ? bcv.z : 0.f;
    t.w = (btv.w == 1.f && bcv.w > 0.f) ? bcv.w : 0.f;
    ((float4*)g_T)[i] = t;
}

// ---------------------------------------------------------------------------
// Kernel 2: horizontal 11-wide box SUM (zero pad), g_T -> g_V1
// ---------------------------------------------------------------------------
__global__ void k_hbox() {
    int c4  = blockIdx.x * blockDim.x + threadIdx.x;
    int row = blockIdx.y;
    if (c4 >= NQ) return;
    int c0 = c4 * 4;
    const float* src = g_T + (size_t)row * RES;
    float v[14];
    #pragma unroll
    for (int d = 0; d < 14; d++) {
        int c = c0 - HALF + d;
        v[d] = (c >= 0 && c < RES) ? __ldg(src + c) : 0.f;
    }
    float s = 0.f;
    #pragma unroll
    for (int d = 0; d < 11; d++) s += v[d];
    float4 o;
    o.x = s;
    s += v[11] - v[0];  o.y = s;
    s += v[12] - v[1];  o.z = s;
    s += v[13] - v[2];  o.w = s;
    ((float4*)g_V1)[(size_t)row * NQ + c4] = o;
}

// ---------------------------------------------------------------------------
// Kernel 3: vertical 11-wide box SUM (zero pad) + build encoded E   (float4)
// ---------------------------------------------------------------------------
__global__ void k_vbox_combine(const float4* __restrict__ bt,
                               const float4* __restrict__ bc,
                               const float4* __restrict__ cpos) {
    int c4  = blockIdx.x * blockDim.x + threadIdx.x;
    int row = blockIdx.y;
    if (c4 >= NQ) return;
    size_t i = (size_t)row * NQ + c4;
    float4 s = make_float4(0.f, 0.f, 0.f, 0.f);
    const float4* V1 = (const float4*)g_V1;
    #pragma unroll
    for (int d = -HALF; d <= HALF; d++) {
        int r = row + d;
        if (r >= 0 && r < RES) {
            float4 t = __ldg(V1 + (size_t)r * NQ + c4);
            s.x += t.x; s.y += t.y; s.z += t.z; s.w += t.w;
        }
    }
    float4 btv = bt[i];
    float4 bcv = bc[i];
    float4 cp  = cpos[i];
    float4 e;
    e.x = (btv.x == 0.f) ? cp.x + s.x * INV_AREA : -bcv.x - 1.f;
    e.y = (btv.y == 0.f) ? cp.y + s.y * INV_AREA : -bcv.y - 1.f;
    e.z = (btv.z == 0.f) ? cp.z + s.z * INV_AREA : -bcv.z - 1.f;
    e.w = (btv.w == 0.f) ? cp.w + s.w * INV_AREA : -bcv.w - 1.f;
    ((float4*)g_E)[i] = e;
}

// ---------------------------------------------------------------------------
// Kernel 4: KF fused Jacobi steps; V register-resident (4 rows/thread).
// Only strip-boundary rows go through smem (double-buffered halo exchange).
// Horizontal neighbors via shfl. One __syncthreads per step.
// ---------------------------------------------------------------------------
#define HALO_STRIDE (NWY * RX)          // one halo plane: 16 rows x 128

template <bool BORDER>
__device__ __forceinline__ void jfuse_body(const float* __restrict__ Vin,
                                           float* __restrict__ Vout,
                                           int isfinal, float* smem) {
    int tx = threadIdx.x & 31;
    int ty = threadIdx.x >> 5;            // 0..15
    int gr0 = blockIdx.y * TY - KF;
    int gc0 = blockIdx.x * TX - KF;
    int cb  = gc0 + tx * 4;
    int r0  = ty * RPT;

    bool is_ledge = BORDER && (cb == 0);
    bool is_redge = BORDER && (cb + 3 == RES - 1);

    // ---- fill: V and E straight into registers ----
    float4 v[RPT], e[RPT];
    #pragma unroll
    for (int j = 0; j < RPT; j++) {
        int r = r0 + j;
        if (!BORDER) {
            size_t off = (size_t)(gr0 + r) * RES + cb;
            v[j] = *(const float4*)(Vin + off);
            e[j] = *(const float4*)(g_E + off);
        } else {
            int gr = min(max(gr0 + r, 0), RES - 1);
            size_t rowoff = (size_t)gr * RES;
            if (cb >= 0 && cb + 3 < RES) {
                v[j] = *(const float4*)(Vin + rowoff + cb);
                e[j] = *(const float4*)(g_E + rowoff + cb);
            } else {
                int c0i = min(max(cb + 0, 0), RES - 1);
                int c1i = min(max(cb + 1, 0), RES - 1);
                int c2i = min(max(cb + 2, 0), RES - 1);
                int c3i = min(max(cb + 3, 0), RES - 1);
                v[j] = make_float4(Vin[rowoff + c0i], Vin[rowoff + c1i],
                                   Vin[rowoff + c2i], Vin[rowoff + c3i]);
                e[j] = make_float4(g_E[rowoff + c0i], g_E[rowoff + c1i],
                                   g_E[rowoff + c2i], g_E[rowoff + c3i]);
            }
        }
    }

    #pragma unroll
    for (int s = 0; s < KF; s++) {
        float* top = smem + (s & 1) * (2 * HALO_STRIDE);
        float* bot = top + HALO_STRIDE;
        // publish strip-boundary rows
        *(float4*)(top + ty * RX + 4 * tx) = v[0];
        *(float4*)(bot + ty * RX + 4 * tx) = v[RPT - 1];
        __syncthreads();
        float4 above = (ty > 0)       ? *(const float4*)(bot + (ty - 1) * RX + 4 * tx) : v[0];
        float4 below = (ty < NWY - 1) ? *(const float4*)(top + (ty + 1) * RX + 4 * tx) : v[RPT - 1];
        bool last = (s == KF - 1);
        float4 pm1 = above;
        #pragma unroll
        for (int j = 0; j < RPT; j++) {
            float4 np1 = (j < RPT - 1) ? v[j + 1] : below;
            float4 cur = v[j];
            float4 up = pm1;
            float4 dn = np1;
            if (BORDER) {
                int grr = gr0 + r0 + j;
                if (grr <= 0)       up = cur;
                if (grr >= RES - 1) dn = cur;
            }
            float lf = __shfl_up_sync(0xffffffffu, cur.w, 1);
            float rg = __shfl_down_sync(0xffffffffu, cur.x, 1);
            if (tx == 0 || is_ledge)  lf = cur.x;
            if (tx == 31 || is_redge) rg = cur.w;
            float4 ee = e[j];
            float4 o;
            o.x = (ee.x >= 0.f) ? 0.25f * (up.x + dn.x + lf    + cur.y) + ee.x : -ee.x - 1.f;
            o.y = (ee.y >= 0.f) ? 0.25f * (up.y + dn.y + cur.x + cur.z) + ee.y : -ee.y - 1.f;
            o.z = (ee.z >= 0.f) ? 0.25f * (up.z + dn.z + cur.y + cur.w) + ee.z : -ee.z - 1.f;
            o.w = (ee.w >= 0.f) ? 0.25f * (up.w + dn.w + cur.z + rg   ) + ee.w : -ee.w - 1.f;
            if (!last) {
                v[j] = o;
            } else {
                int r = r0 + j;
                if (r >= KF && r < RY - KF && tx >= 1 && tx <= 30) {
                    bool ok = true;
                    if (BORDER) ok = (gr0 + r) < RES && (cb + 3) < RES;
                    if (ok) {
                        if (isfinal) {
                            o.x = (o.x >= 1.f) ? 0.95f : o.x;
                            o.y = (o.y >= 1.f) ? 0.95f : o.y;
                            o.z = (o.z >= 1.f) ? 0.95f : o.z;
                            o.w = (o.w >= 1.f) ? 0.95f : o.w;
                        }
                        *(float4*)(Vout + (size_t)(gr0 + r) * RES + cb) = o;
                    }
                }
            }
            pm1 = cur;
        }
    }
}

__global__ __launch_bounds__(NTHREADS, 2)
void k_jfuse(const float* __restrict__ Vin, float* __restrict__ Vout, int isfinal) {
    __shared__ float smem[2 * 2 * HALO_STRIDE];   // 32 KB
    bool border = (blockIdx.x == 0) | (blockIdx.x == gridDim.x - 1) |
                  (blockIdx.y == 0) | (blockIdx.y == gridDim.y - 1);
    if (!border) jfuse_body<false>(Vin, Vout, isfinal, smem);
    else         jfuse_body<true >(Vin, Vout, isfinal, smem);
}

// ---------------------------------------------------------------------------
extern "C" void kernel_launch(void* const* d_in, const int* in_sizes, int n_in,
                              void* d_out, int out_size) {
    const float* x  = (const float*)d_in[0];
    const float* bt = (const float*)d_in[1];
    const float* bc = (const float*)d_in[2];
    const float* C  = (const float*)d_in[3];
    float* out  = (float*)d_out;
    float* cpos = out + (size_t)NTOT;

    // init (float4)
    {
        dim3 b(256), g((NTOT / 4 + 255) / 256);
        k_init<<<g, b>>>((const float4*)x, (const float4*)bt,
                         (const float4*)bc, (const float4*)C,
                         (float4*)cpos);
    }
    // separable 11x11 box filter (R3 version — proven faster than fused)
    {
        dim3 b(256, 1), g(NQ / 256, RES);
        k_hbox<<<g, b>>>();
        k_vbox_combine<<<g, b>>>((const float4*)bt, (const float4*)bc,
                                 (const float4*)cpos);
    }
    // 20 Jacobi iters = 5 fused passes of KF=4
    {
        float *dv0, *dv1;
        cudaGetSymbolAddress((void**)&dv0, g_V0);
        cudaGetSymbolAddress((void**)&dv1, g_V1);
        dim3 b(NTHREADS), g((RES + TX - 1) / TX, (RES + TY - 1) / TY);   // 35 x 74
        k_jfuse<<<g, b>>>(dv0, dv1, 0);
        k_jfuse<<<g, b>>>(dv1, dv0, 0);
        k_jfuse<<<g, b>>>(dv0, dv1, 0);
        k_jfuse<<<g, b>>>(dv1, dv0, 0);
        k_jfuse<<<g, b>>>(dv0, out, 1);   // final 4 steps + clamp
    }
}

// round 7
// speedup vs baseline: 1.3306x; 1.0896x over previous
#include <cuda_runtime.h>

#define RES 4096
#define NQ  (RES / 4)
#define NTOT (RES * RES)
#define HALF 5
#define INV_AREA (1.0f / 121.0f)

// Temporal-blocked Jacobi tile params
#define KF 5                 // fused steps per pass (20 = 4 passes x 5)
#define HX 8                 // horizontal halo (float4-aligned, >= KF)
#define HY 5                 // vertical halo (= KF)
#define RX 128               // region cols (32 float4)
#define RY 64                // region rows
#define TX (RX - 2 * HX)     // 112 valid output cols
#define TY (RY - 2 * HY)     // 54 valid output rows
#define NTHREADS 512
#define RPT 4                // rows per thread
#define NWY 16               // warps (strips) in y
#define HALO_STRIDE (NWY * RX)

// Scratch (device globals — no allocation allowed)
__device__ float g_V0[NTOT];
__device__ float g_V1[NTOT];
__device__ float g_E[NTOT];

// ---------------------------------------------------------------------------
// Kernel 1: fused init + horizontal box sum.
// Per block: one row, 1024 cols (256 threads x float4).
// Writes cpos, V0, and the 11-wide horizontal sum of T (into g_V1).
// T = (bt==1 && bc>0) ? bc : 0 is computed on the fly, staged in smem.
// ---------------------------------------------------------------------------
__global__ __launch_bounds__(256)
void k_init_hbox(const float4* __restrict__ x,
                 const float4* __restrict__ bt,
                 const float4* __restrict__ bc,
                 const float4* __restrict__ C,
                 float4* __restrict__ cpos_out,
                 const float* __restrict__ bt_s,
                 const float* __restrict__ bc_s) {
    __shared__ float sT[1024 + 16];     // center at offset 8
    int tid = threadIdx.x;
    int row = blockIdx.y;
    int c0  = blockIdx.x * 1024;        // block's first col
    int cb  = c0 + tid * 4;             // this thread's first col
    size_t i4 = ((size_t)row * RES + cb) / 4;

    float4 btv = bt[i4];
    float4 bcv = bc[i4];
    float4 cv  = C[i4];
    float4 xv  = x[i4];
    float4 cp;
    cp.x = fmaxf(cv.x, 0.f); cp.y = fmaxf(cv.y, 0.f);
    cp.z = fmaxf(cv.z, 0.f); cp.w = fmaxf(cv.w, 0.f);
    cpos_out[i4] = cp;
    float4 v0;
    v0.x = (btv.x > 0.f) ? bcv.x : xv.x;
    v0.y = (btv.y > 0.f) ? bcv.y : xv.y;
    v0.z = (btv.z > 0.f) ? bcv.z : xv.z;
    v0.w = (btv.w > 0.f) ? bcv.w : xv.w;
    ((float4*)g_V0)[i4] = v0;
    int lc = tid * 4;
    sT[8 + lc + 0] = (btv.x == 1.f && bcv.x > 0.f) ? bcv.x : 0.f;
    sT[8 + lc + 1] = (btv.y == 1.f && bcv.y > 0.f) ? bcv.y : 0.f;
    sT[8 + lc + 2] = (btv.z == 1.f && bcv.z > 0.f) ? bcv.z : 0.f;
    sT[8 + lc + 3] = (btv.w == 1.f && bcv.w > 0.f) ? bcv.w : 0.f;
    // halos (5 left, 5 right), zero-pad at grid edges
    if (tid < 5) {
        int gc = c0 - 5 + tid;
        float t = 0.f;
        if (gc >= 0) {
            size_t gi = (size_t)row * RES + gc;
            float b = bt_s[gi], v = bc_s[gi];
            t = (b == 1.f && v > 0.f) ? v : 0.f;
        }
        sT[3 + tid] = t;
    } else if (tid < 10) {
        int gc = c0 + 1024 + (tid - 5);
        float t = 0.f;
        if (gc < RES) {
            size_t gi = (size_t)row * RES + gc;
            float b = bt_s[gi], v = bc_s[gi];
            t = (b == 1.f && v > 0.f) ? v : 0.f;
        }
        sT[8 + 1024 + (tid - 5)] = t;
    }
    __syncthreads();
    // 11-wide sliding sums for 4 outputs
    float w[14];
    #pragma unroll
    for (int d = 0; d < 14; d++) w[d] = sT[3 + lc + d];
    float s = 0.f;
    #pragma unroll
    for (int d = 0; d < 11; d++) s += w[d];
    float4 o;
    o.x = s;
    s += w[11] - w[0];  o.y = s;
    s += w[12] - w[1];  o.z = s;
    s += w[13] - w[2];  o.w = s;
    ((float4*)g_V1)[i4] = o;
}

// ---------------------------------------------------------------------------
// Kernel 2: vertical 11-wide box SUM (zero pad) + build encoded E   (float4)
// ---------------------------------------------------------------------------
__global__ void k_vbox_combine(const float4* __restrict__ bt,
                               const float4* __restrict__ bc,
                               const float4* __restrict__ cpos) {
    int c4  = blockIdx.x * blockDim.x + threadIdx.x;
    int row = blockIdx.y;
    if (c4 >= NQ) return;
    size_t i = (size_t)row * NQ + c4;
    float4 s = make_float4(0.f, 0.f, 0.f, 0.f);
    const float4* V1 = (const float4*)g_V1;
    #pragma unroll
    for (int d = -HALF; d <= HALF; d++) {
        int r = row + d;
        if (r >= 0 && r < RES) {
            float4 t = __ldg(V1 + (size_t)r * NQ + c4);
            s.x += t.x; s.y += t.y; s.z += t.z; s.w += t.w;
        }
    }
    float4 btv = bt[i];
    float4 bcv = bc[i];
    float4 cp  = cpos[i];
    float4 e;
    e.x = (btv.x == 0.f) ? cp.x + s.x * INV_AREA : -bcv.x - 1.f;
    e.y = (btv.y == 0.f) ? cp.y + s.y * INV_AREA : -bcv.y - 1.f;
    e.z = (btv.z == 0.f) ? cp.z + s.z * INV_AREA : -bcv.z - 1.f;
    e.w = (btv.w == 0.f) ? cp.w + s.w * INV_AREA : -bcv.w - 1.f;
    ((float4*)g_E)[i] = e;
}

// ---------------------------------------------------------------------------
// Kernel 3: KF fused Jacobi steps; V register-resident (4 rows/thread).
// Strip-boundary rows via double-buffered smem halo; shfls HOISTED per step
// so their 26-cyc latency overlaps instead of serializing.
// ---------------------------------------------------------------------------
template <bool BORDER>
__device__ __forceinline__ void jfuse_body(const float* __restrict__ Vin,
                                           float* __restrict__ Vout,
                                           int isfinal, float* smem) {
    int tx = threadIdx.x & 31;
    int ty = threadIdx.x >> 5;            // 0..15
    int gr0 = blockIdx.y * TY - HY;
    int gc0 = blockIdx.x * TX - HX;
    int cb  = gc0 + tx * 4;
    int r0  = ty * RPT;

    bool is_ledge = BORDER && (cb == 0);
    bool is_redge = BORDER && (cb + 3 == RES - 1);

    // ---- fill: V and E straight into registers ----
    float4 v[RPT], e[RPT];
    #pragma unroll
    for (int j = 0; j < RPT; j++) {
        int r = r0 + j;
        if (!BORDER) {
            size_t off = (size_t)(gr0 + r) * RES + cb;
            v[j] = *(const float4*)(Vin + off);
            e[j] = *(const float4*)(g_E + off);
        } else {
            int gr = min(max(gr0 + r, 0), RES - 1);
            size_t rowoff = (size_t)gr * RES;
            if (cb >= 0 && cb + 3 < RES) {
                v[j] = *(const float4*)(Vin + rowoff + cb);
                e[j] = *(const float4*)(g_E + rowoff + cb);
            } else {
                int c0i = min(max(cb + 0, 0), RES - 1);
                int c1i = min(max(cb + 1, 0), RES - 1);
                int c2i = min(max(cb + 2, 0), RES - 1);
                int c3i = min(max(cb + 3, 0), RES - 1);
                v[j] = make_float4(Vin[rowoff + c0i], Vin[rowoff + c1i],
                                   Vin[rowoff + c2i], Vin[rowoff + c3i]);
                e[j] = make_float4(g_E[rowoff + c0i], g_E[rowoff + c1i],
                                   g_E[rowoff + c2i], g_E[rowoff + c3i]);
            }
        }
    }

    #pragma unroll
    for (int s = 0; s < KF; s++) {
        float* top = smem + (s & 1) * (2 * HALO_STRIDE);
        float* bot = top + HALO_STRIDE;
        // publish strip-boundary rows
        *(float4*)(top + ty * RX + 4 * tx) = v[0];
        *(float4*)(bot + ty * RX + 4 * tx) = v[RPT - 1];
        // hoisted independent shfls — latency overlaps
        float lf[RPT], rg[RPT];
        #pragma unroll
        for (int j = 0; j < RPT; j++) {
            lf[j] = __shfl_up_sync(0xffffffffu, v[j].w, 1);
            rg[j] = __shfl_down_sync(0xffffffffu, v[j].x, 1);
        }
        __syncthreads();
        float4 above = (ty > 0)       ? *(const float4*)(bot + (ty - 1) * RX + 4 * tx) : v[0];
        float4 below = (ty < NWY - 1) ? *(const float4*)(top + (ty + 1) * RX + 4 * tx) : v[RPT - 1];
        bool last = (s == KF - 1);
        float4 pm1 = above;
        #pragma unroll
        for (int j = 0; j < RPT; j++) {
            float4 np1 = (j < RPT - 1) ? v[j + 1] : below;
            float4 cur = v[j];
            float4 up = pm1;
            float4 dn = np1;
            if (BORDER) {
                int grr = gr0 + r0 + j;
                if (grr <= 0)       up = cur;
                if (grr >= RES - 1) dn = cur;
            }
            float lfj = lf[j], rgj = rg[j];
            if (tx == 0 || is_ledge)  lfj = cur.x;
            if (tx == 31 || is_redge) rgj = cur.w;
            float4 ee = e[j];
            float4 o;
            o.x = (ee.x >= 0.f) ? 0.25f * (up.x + dn.x + lfj   + cur.y) + ee.x : -ee.x - 1.f;
            o.y = (ee.y >= 0.f) ? 0.25f * (up.y + dn.y + cur.x + cur.z) + ee.y : -ee.y - 1.f;
            o.z = (ee.z >= 0.f) ? 0.25f * (up.z + dn.z + cur.y + cur.w) + ee.z : -ee.z - 1.f;
            o.w = (ee.w >= 0.f) ? 0.25f * (up.w + dn.w + cur.z + rgj  ) + ee.w : -ee.w - 1.f;
            if (!last) {
                v[j] = o;
            } else {
                int r = r0 + j;
                if (r >= HY && r < RY - HY && tx >= 2 && tx <= 29) {
                    bool ok = true;
                    if (BORDER) ok = (gr0 + r) < RES && (cb + 3) < RES;
                    if (ok) {
                        if (isfinal) {
                            o.x = (o.x >= 1.f) ? 0.95f : o.x;
                            o.y = (o.y >= 1.f) ? 0.95f : o.y;
                            o.z = (o.z >= 1.f) ? 0.95f : o.z;
                            o.w = (o.w >= 1.f) ? 0.95f : o.w;
                        }
                        *(float4*)(Vout + (size_t)(gr0 + r) * RES + cb) = o;
                    }
                }
            }
            pm1 = cur;
        }
    }
}

__global__ __launch_bounds__(NTHREADS, 2)
void k_jfuse(const float* __restrict__ Vin, float* __restrict__ Vout, int isfinal) {
    __shared__ float smem[2 * 2 * HALO_STRIDE];   // 32 KB
    bool border = (blockIdx.x == 0) | (blockIdx.x == gridDim.x - 1) |
                  (blockIdx.y == 0) | (blockIdx.y == gridDim.y - 1);
    if (!border) jfuse_body<false>(Vin, Vout, isfinal, smem);
    else         jfuse_body<true >(Vin, Vout, isfinal, smem);
}

// ---------------------------------------------------------------------------
extern "C" void kernel_launch(void* const* d_in, const int* in_sizes, int n_in,
                              void* d_out, int out_size) {
    const float* x  = (const float*)d_in[0];
    const float* bt = (const float*)d_in[1];
    const float* bc = (const float*)d_in[2];
    const float* C  = (const float*)d_in[3];
    float* out  = (float*)d_out;
    float* cpos = out + (size_t)NTOT;

    // fused init + horizontal box sum
    {
        dim3 b(256), g(RES / 1024, RES);   // 4 x 4096
        k_init_hbox<<<g, b>>>((const float4*)x, (const float4*)bt,
                              (const float4*)bc, (const float4*)C,
                              (float4*)cpos, bt, bc);
    }
    // vertical box sum + E build
    {
        dim3 b(256, 1), g(NQ / 256, RES);
        k_vbox_combine<<<g, b>>>((const float4*)bt, (const float4*)bc,
                                 (const float4*)cpos);
    }
    // 20 Jacobi iters = 4 fused passes of KF=5
    {
        float *dv0, *dv1;
        cudaGetSymbolAddress((void**)&dv0, g_V0);
        cudaGetSymbolAddress((void**)&dv1, g_V1);
        dim3 b(NTHREADS), g((RES + TX - 1) / TX, (RES + TY - 1) / TY);   // 37 x 76
        k_jfuse<<<g, b>>>(dv0, dv1, 0);
        k_jfuse<<<g, b>>>(dv1, dv0, 0);
        k_jfuse<<<g, b>>>(dv0, dv1, 0);
        k_jfuse<<<g, b>>>(dv1, out, 1);   // final 5 steps + clamp
    }
}

// round 11
// speedup vs baseline: 1.4885x; 1.1186x over previous
#include <cuda_runtime.h>

#define RES 4096
#define NQ  (RES / 4)
#define NTOT (RES * RES)
#define HALF 5
#define INV_AREA (1.0f / 121.0f)

// Temporal-blocked Jacobi tile params
#define KF 5                 // fused steps per pass (20 = 4 passes x 5)
#define HX 8                 // horizontal halo (float4-aligned, >= KF)
#define HY 5                 // vertical halo (= KF)
#define RX 128               // region cols (32 float4)
#define RY 64                // region rows
#define TX (RX - 2 * HX)     // 112 valid output cols
#define TY (RY - 2 * HY)     // 54 valid output rows
#define NTHREADS 512
#define RPT 4                // rows per thread
#define NWY 16               // warps (strips) in y
#define HALO_STRIDE (NWY * RX)

// Scratch (device globals — no allocation allowed)
__device__ float g_V0[NTOT];
__device__ float g_V1[NTOT];
__device__ float g_E[NTOT];

// ---------------------------------------------------------------------------
// Packed f32x2 helpers (sm_103a): 2 components per instruction.
// ---------------------------------------------------------------------------
__device__ __forceinline__ float2 addx2(float2 a, float2 b) {
    float2 r;
    asm("{\n\t.reg .b64 ra, rb, rc;\n\t"
        "mov.b64 ra, {%2, %3};\n\t"
        "mov.b64 rb, {%4, %5};\n\t"
        "add.rn.f32x2 rc, ra, rb;\n\t"
        "mov.b64 {%0, %1}, rc;\n\t}"
        : "=f"(r.x), "=f"(r.y)
        : "f"(a.x), "f"(a.y), "f"(b.x), "f"(b.y));
    return r;
}
__device__ __forceinline__ float2 fmax2(float2 a, float2 b, float2 c) {
    float2 r;
    asm("{\n\t.reg .b64 ra, rb, rc, rd;\n\t"
        "mov.b64 ra, {%2, %3};\n\t"
        "mov.b64 rb, {%4, %5};\n\t"
        "mov.b64 rc, {%6, %7};\n\t"
        "fma.rn.f32x2 rd, ra, rb, rc;\n\t"
        "mov.b64 {%0, %1}, rd;\n\t}"
        : "=f"(r.x), "=f"(r.y)
        : "f"(a.x), "f"(a.y), "f"(b.x), "f"(b.y), "f"(c.x), "f"(c.y));
    return r;
}

// ---------------------------------------------------------------------------
// Kernel 1: fused init + horizontal box sum.
// ---------------------------------------------------------------------------
__global__ __launch_bounds__(256)
void k_init_hbox(const float4* __restrict__ x,
                 const float4* __restrict__ bt,
                 const float4* __restrict__ bc,
                 const float4* __restrict__ C,
                 float4* __restrict__ cpos_out,
                 const float* __restrict__ bt_s,
                 const float* __restrict__ bc_s) {
    __shared__ float sT[1024 + 16];     // center at offset 8
    int tid = threadIdx.x;
    int row = blockIdx.y;
    int c0  = blockIdx.x * 1024;
    int cb  = c0 + tid * 4;
    size_t i4 = ((size_t)row * RES + cb) / 4;

    float4 btv = bt[i4];
    float4 bcv = bc[i4];
    float4 cv  = C[i4];
    float4 xv  = x[i4];
    float4 cp;
    cp.x = fmaxf(cv.x, 0.f); cp.y = fmaxf(cv.y, 0.f);
    cp.z = fmaxf(cv.z, 0.f); cp.w = fmaxf(cv.w, 0.f);
    cpos_out[i4] = cp;
    float4 v0;
    v0.x = (btv.x > 0.f) ? bcv.x : xv.x;
    v0.y = (btv.y > 0.f) ? bcv.y : xv.y;
    v0.z = (btv.z > 0.f) ? bcv.z : xv.z;
    v0.w = (btv.w > 0.f) ? bcv.w : xv.w;
    ((float4*)g_V0)[i4] = v0;
    int lc = tid * 4;
    sT[8 + lc + 0] = (btv.x == 1.f && bcv.x > 0.f) ? bcv.x : 0.f;
    sT[8 + lc + 1] = (btv.y == 1.f && bcv.y > 0.f) ? bcv.y : 0.f;
    sT[8 + lc + 2] = (btv.z == 1.f && bcv.z > 0.f) ? bcv.z : 0.f;
    sT[8 + lc + 3] = (btv.w == 1.f && bcv.w > 0.f) ? bcv.w : 0.f;
    if (tid < 5) {
        int gc = c0 - 5 + tid;
        float t = 0.f;
        if (gc >= 0) {
            size_t gi = (size_t)row * RES + gc;
            float b = bt_s[gi], v = bc_s[gi];
            t = (b == 1.f && v > 0.f) ? v : 0.f;
        }
        sT[3 + tid] = t;
    } else if (tid < 10) {
        int gc = c0 + 1024 + (tid - 5);
        float t = 0.f;
        if (gc < RES) {
            size_t gi = (size_t)row * RES + gc;
            float b = bt_s[gi], v = bc_s[gi];
            t = (b == 1.f && v > 0.f) ? v : 0.f;
        }
        sT[8 + 1024 + (tid - 5)] = t;
    }
    __syncthreads();
    float w[14];
    #pragma unroll
    for (int d = 0; d < 14; d++) w[d] = sT[3 + lc + d];
    float s = 0.f;
    #pragma unroll
    for (int d = 0; d < 11; d++) s += w[d];
    float4 o;
    o.x = s;
    s += w[11] - w[0];  o.y = s;
    s += w[12] - w[1];  o.z = s;
    s += w[13] - w[2];  o.w = s;
    ((float4*)g_V1)[i4] = o;
}

// ---------------------------------------------------------------------------
// Kernel 2: vertical 11-wide box SUM (zero pad) + build encoded E   (float4)
// ---------------------------------------------------------------------------
__global__ void k_vbox_combine(const float4* __restrict__ bt,
                               const float4* __restrict__ bc,
                               const float4* __restrict__ cpos) {
    int c4  = blockIdx.x * blockDim.x + threadIdx.x;
    int row = blockIdx.y;
    if (c4 >= NQ) return;
    size_t i = (size_t)row * NQ + c4;
    float4 s = make_float4(0.f, 0.f, 0.f, 0.f);
    const float4* V1 = (const float4*)g_V1;
    #pragma unroll
    for (int d = -HALF; d <= HALF; d++) {
        int r = row + d;
        if (r >= 0 && r < RES) {
            float4 t = __ldg(V1 + (size_t)r * NQ + c4);
            s.x += t.x; s.y += t.y; s.z += t.z; s.w += t.w;
        }
    }
    float4 btv = bt[i];
    float4 bcv = bc[i];
    float4 cp  = cpos[i];
    float4 e;
    e.x = (btv.x == 0.f) ? cp.x + s.x * INV_AREA : -bcv.x - 1.f;
    e.y = (btv.y == 0.f) ? cp.y + s.y * INV_AREA : -bcv.y - 1.f;
    e.z = (btv.z == 0.f) ? cp.z + s.z * INV_AREA : -bcv.z - 1.f;
    e.w = (btv.w == 0.f) ? cp.w + s.w * INV_AREA : -bcv.w - 1.f;
    ((float4*)g_E)[i] = e;
}

// ---------------------------------------------------------------------------
// Kernel 3: KF fused Jacobi steps; V register-resident (4 rows/thread).
// E expanded ONCE at fill into (w, a): step update is branchless
//   o = w * (up+dn+lf+rg) + a   via packed f32x2 FFMA.
// ---------------------------------------------------------------------------
template <bool BORDER, int FINAL>
__device__ __forceinline__ void jfuse_body(const float* __restrict__ Vin,
                                           float* __restrict__ Vout,
                                           float* smem) {
    int tx = threadIdx.x & 31;
    int ty = threadIdx.x >> 5;            // 0..15
    int gr0 = blockIdx.y * TY - HY;
    int gc0 = blockIdx.x * TX - HX;
    int cb  = gc0 + tx * 4;
    int r0  = ty * RPT;

    bool is_ledge = BORDER && (cb == 0);
    bool is_redge = BORDER && (cb + 3 == RES - 1);

    // ---- fill: V into regs; E -> (w, a) regs ----
    float4 v[RPT], w[RPT], a[RPT];
    #pragma unroll
    for (int j = 0; j < RPT; j++) {
        int r = r0 + j;
        float4 ev;
        if (!BORDER) {
            size_t off = (size_t)(gr0 + r) * RES + cb;
            v[j] = *(const float4*)(Vin + off);
            ev   = *(const float4*)(g_E + off);
        } else {
            int gr = min(max(gr0 + r, 0), RES - 1);
            size_t rowoff = (size_t)gr * RES;
            if (cb >= 0 && cb + 3 < RES) {
                v[j] = *(const float4*)(Vin + rowoff + cb);
                ev   = *(const float4*)(g_E + rowoff + cb);
            } else {
                int c0i = min(max(cb + 0, 0), RES - 1);
                int c1i = min(max(cb + 1, 0), RES - 1);
                int c2i = min(max(cb + 2, 0), RES - 1);
                int c3i = min(max(cb + 3, 0), RES - 1);
                v[j] = make_float4(Vin[rowoff + c0i], Vin[rowoff + c1i],
                                   Vin[rowoff + c2i], Vin[rowoff + c3i]);
                ev   = make_float4(g_E[rowoff + c0i], g_E[rowoff + c1i],
                                   g_E[rowoff + c2i], g_E[rowoff + c3i]);
            }
        }
        w[j].x = (ev.x >= 0.f) ? 0.25f : 0.f;
        w[j].y = (ev.y >= 0.f) ? 0.25f : 0.f;
        w[j].z = (ev.z >= 0.f) ? 0.25f : 0.f;
        w[j].w = (ev.w >= 0.f) ? 0.25f : 0.f;
        a[j].x = (ev.x >= 0.f) ? ev.x : -ev.x - 1.f;
        a[j].y = (ev.y >= 0.f) ? ev.y : -ev.y - 1.f;
        a[j].z = (ev.z >= 0.f) ? ev.z : -ev.z - 1.f;
        a[j].w = (ev.w >= 0.f) ? ev.w : -ev.w - 1.f;
    }

    #pragma unroll
    for (int s = 0; s < KF; s++) {
        float* top = smem + (s & 1) * (2 * HALO_STRIDE);
        float* bot = top + HALO_STRIDE;
        *(float4*)(top + ty * RX + 4 * tx) = v[0];
        *(float4*)(bot + ty * RX + 4 * tx) = v[RPT - 1];
        __syncthreads();
        float4 above = (ty > 0)       ? *(const float4*)(bot + (ty - 1) * RX + 4 * tx) : v[0];
        float4 below = (ty < NWY - 1) ? *(const float4*)(top + (ty + 1) * RX + 4 * tx) : v[RPT - 1];
        bool last = (s == KF - 1);
        float4 pm1 = above;
        #pragma unroll
        for (int j = 0; j < RPT; j++) {
            float4 np1 = (j < RPT - 1) ? v[j + 1] : below;
            float4 cur = v[j];
            float4 up = pm1;
            float4 dn = np1;
            if (BORDER) {
                int grr = gr0 + r0 + j;
                if (grr <= 0)       up = cur;
                if (grr >= RES - 1) dn = cur;
            }
            float lf = __shfl_up_sync(0xffffffffu, cur.w, 1);
            float rg = __shfl_down_sync(0xffffffffu, cur.x, 1);
            if (tx == 0 || is_ledge)  lf = cur.x;
            if (tx == 31 || is_redge) rg = cur.w;
            // t = up + dn (packed)
            float2 t01 = addx2(make_float2(up.x, up.y), make_float2(dn.x, dn.y));
            float2 t23 = addx2(make_float2(up.z, up.w), make_float2(dn.z, dn.w));
            // h = horizontal pair sums (scalar cross terms)
            float h0 = lf    + cur.y;
            float h1 = cur.x + cur.z;
            float h2 = cur.y + cur.w;
            float h3 = cur.z + rg;
            float2 u01 = addx2(t01, make_float2(h0, h1));
            float2 u23 = addx2(t23, make_float2(h2, h3));
            // o = w * u + a  (packed FFMA)
            float2 o01 = fmax2(make_float2(w[j].x, w[j].y), u01,
                               make_float2(a[j].x, a[j].y));
            float2 o23 = fmax2(make_float2(w[j].z, w[j].w), u23,
                               make_float2(a[j].z, a[j].w));
            float4 o = make_float4(o01.x, o01.y, o23.x, o23.y);
            if (!last) {
                v[j] = o;
            } else {
                int r = r0 + j;
                if (r >= HY && r < RY - HY && tx >= 2 && tx <= 29) {
                    bool ok = true;
                    if (BORDER) ok = (gr0 + r) < RES && (cb + 3) < RES;
                    if (ok) {
                        if (FINAL) {
                            o.x = (o.x >= 1.f) ? 0.95f : o.x;
                            o.y = (o.y >= 1.f) ? 0.95f : o.y;
                            o.z = (o.z >= 1.f) ? 0.95f : o.z;
                            o.w = (o.w >= 1.f) ? 0.95f : o.w;
                        }
                        *(float4*)(Vout + (size_t)(gr0 + r) * RES + cb) = o;
                    }
                }
            }
            pm1 = cur;
        }
    }
}

template <int FINAL>
__global__ __launch_bounds__(NTHREADS, 2)
void k_jfuse(const float* __restrict__ Vin, float* __restrict__ Vout) {
    __shared__ float smem[2 * 2 * HALO_STRIDE];   // 32 KB
    bool border = (blockIdx.x == 0) | (blockIdx.x == gridDim.x - 1) |
                  (blockIdx.y == 0) | (blockIdx.y == gridDim.y - 1);
    if (!border) jfuse_body<false, FINAL>(Vin, Vout, smem);
    else         jfuse_body<true,  FINAL>(Vin, Vout, smem);
}

// ---------------------------------------------------------------------------
extern "C" void kernel_launch(void* const* d_in, const int* in_sizes, int n_in,
                              void* d_out, int out_size) {
    const float* x  = (const float*)d_in[0];
    const float* bt = (const float*)d_in[1];
    const float* bc = (const float*)d_in[2];
    const float* C  = (const float*)d_in[3];
    float* out  = (float*)d_out;
    float* cpos = out + (size_t)NTOT;

    // fused init + horizontal box sum
    {
        dim3 b(256), g(RES / 1024, RES);   // 4 x 4096
        k_init_hbox<<<g, b>>>((const float4*)x, (const float4*)bt,
                              (const float4*)bc, (const float4*)C,
                              (float4*)cpos, bt, bc);
    }
    // vertical box sum + E build
    {
        dim3 b(256, 1), g(NQ / 256, RES);
        k_vbox_combine<<<g, b>>>((const float4*)bt, (const float4*)bc,
                                 (const float4*)cpos);
    }
    // 20 Jacobi iters = 4 fused passes of KF=5
    {
        float *dv0, *dv1;
        cudaGetSymbolAddress((void**)&dv0, g_V0);
        cudaGetSymbolAddress((void**)&dv1, g_V1);
        dim3 b(NTHREADS), g((RES + TX - 1) / TX, (RES + TY - 1) / TY);   // 37 x 76
        k_jfuse<0><<<g, b>>>(dv0, dv1);
        k_jfuse<0><<<g, b>>>(dv1, dv0);
        k_jfuse<0><<<g, b>>>(dv0, dv1);
        k_jfuse<1><<<g, b>>>(dv1, out);   // final 5 steps + clamp
    }
}

// round 14
// speedup vs baseline: 1.6630x; 1.1173x over previous
#include <cuda_runtime.h>

#define RES 4096
#define NQ  (RES / 4)
#define NTOT (RES * RES)
#define HALF 5
#define INV_AREA (1.0f / 121.0f)

// Temporal-blocked Jacobi tile params (20 iters = 7 + 7 + 6)
#define HX 8                 // horizontal halo (float4-aligned, >= 7)
#define HY 7                 // vertical halo (= max KF)
#define RX 128               // region cols (32 float4)
#define RY 64                // region rows
#define TX (RX - 2 * HX)     // 112 valid output cols
#define TY (RY - 2 * HY)     // 50 valid output rows
#define NTHREADS 512
#define RPT 4                // rows per thread
#define NWY 16               // warps (strips) in y
#define HALO_STRIDE (NWY * RX)

// Scratch (device globals — no allocation allowed)
__device__ float g_V0[NTOT];   // B (packed base) during prologue, then ping-pong
__device__ float g_V1[NTOT];   // hbox sums during prologue, then ping-pong
__device__ float g_E[NTOT];

// ---------------------------------------------------------------------------
// Packed f32x2 helpers (sm_103a)
// ---------------------------------------------------------------------------
__device__ __forceinline__ float2 addx2(float2 a, float2 b) {
    float2 r;
    asm("{\n\t.reg .b64 ra, rb, rc;\n\t"
        "mov.b64 ra, {%2, %3};\n\t"
        "mov.b64 rb, {%4, %5};\n\t"
        "add.rn.f32x2 rc, ra, rb;\n\t"
        "mov.b64 {%0, %1}, rc;\n\t}"
        : "=f"(r.x), "=f"(r.y)
        : "f"(a.x), "f"(a.y), "f"(b.x), "f"(b.y));
    return r;
}
__device__ __forceinline__ float2 fmax2(float2 a, float2 b, float2 c) {
    float2 r;
    asm("{\n\t.reg .b64 ra, rb, rc, rd;\n\t"
        "mov.b64 ra, {%2, %3};\n\t"
        "mov.b64 rb, {%4, %5};\n\t"
        "mov.b64 rc, {%6, %7};\n\t"
        "fma.rn.f32x2 rd, ra, rb, rc;\n\t"
        "mov.b64 {%0, %1}, rd;\n\t}"
        : "=f"(r.x), "=f"(r.y)
        : "f"(a.x), "f"(a.y), "f"(b.x), "f"(b.y), "f"(c.x), "f"(c.y));
    return r;
}

// ---------------------------------------------------------------------------
// Kernel 1: fused init + horizontal box sum.
// Writes cpos (output), B (packed base -> g_V0), hsum (-> g_V1).
//   B = interior ? cpos : -bc-1
// ---------------------------------------------------------------------------
__global__ __launch_bounds__(256)
void k_init_hbox(const float4* __restrict__ bt,
                 const float4* __restrict__ bc,
                 const float4* __restrict__ C,
                 float4* __restrict__ cpos_out,
                 const float* __restrict__ bt_s,
                 const float* __restrict__ bc_s) {
    __shared__ float sT[1024 + 16];     // center at offset 8
    int tid = threadIdx.x;
    int row = blockIdx.y;
    int c0  = blockIdx.x * 1024;
    int cb  = c0 + tid * 4;
    size_t i4 = ((size_t)row * RES + cb) / 4;

    float4 btv = bt[i4];
    float4 bcv = bc[i4];
    float4 cv  = C[i4];
    float4 cp;
    cp.x = fmaxf(cv.x, 0.f); cp.y = fmaxf(cv.y, 0.f);
    cp.z = fmaxf(cv.z, 0.f); cp.w = fmaxf(cv.w, 0.f);
    cpos_out[i4] = cp;
    float4 B;
    B.x = (btv.x == 0.f) ? cp.x : -bcv.x - 1.f;
    B.y = (btv.y == 0.f) ? cp.y : -bcv.y - 1.f;
    B.z = (btv.z == 0.f) ? cp.z : -bcv.z - 1.f;
    B.w = (btv.w == 0.f) ? cp.w : -bcv.w - 1.f;
    ((float4*)g_V0)[i4] = B;
    int lc = tid * 4;
    sT[8 + lc + 0] = (btv.x == 1.f && bcv.x > 0.f) ? bcv.x : 0.f;
    sT[8 + lc + 1] = (btv.y == 1.f && bcv.y > 0.f) ? bcv.y : 0.f;
    sT[8 + lc + 2] = (btv.z == 1.f && bcv.z > 0.f) ? bcv.z : 0.f;
    sT[8 + lc + 3] = (btv.w == 1.f && bcv.w > 0.f) ? bcv.w : 0.f;
    if (tid < 5) {
        int gc = c0 - 5 + tid;
        float t = 0.f;
        if (gc >= 0) {
            size_t gi = (size_t)row * RES + gc;
            float b = bt_s[gi], v = bc_s[gi];
            t = (b == 1.f && v > 0.f) ? v : 0.f;
        }
        sT[3 + tid] = t;
    } else if (tid < 10) {
        int gc = c0 + 1024 + (tid - 5);
        float t = 0.f;
        if (gc < RES) {
            size_t gi = (size_t)row * RES + gc;
            float b = bt_s[gi], v = bc_s[gi];
            t = (b == 1.f && v > 0.f) ? v : 0.f;
        }
        sT[8 + 1024 + (tid - 5)] = t;
    }
    __syncthreads();
    float w[14];
    #pragma unroll
    for (int d = 0; d < 14; d++) w[d] = sT[3 + lc + d];
    float s = 0.f;
    #pragma unroll
    for (int d = 0; d < 11; d++) s += w[d];
    float4 o;
    o.x = s;
    s += w[11] - w[0];  o.y = s;
    s += w[12] - w[1];  o.z = s;
    s += w[13] - w[2];  o.w = s;
    ((float4*)g_V1)[i4] = o;
}

// ---------------------------------------------------------------------------
// Kernel 2: vertical 11-wide box SUM (zero pad) + build encoded E.
// Reads B (g_V0) + hsum (g_V1) only.  E = B>=0 ? B + s*INV_AREA : B.
// ---------------------------------------------------------------------------
__global__ void k_vbox_combine() {
    int c4  = blockIdx.x * blockDim.x + threadIdx.x;
    int row = blockIdx.y;
    if (c4 >= NQ) return;
    size_t i = (size_t)row * NQ + c4;
    float4 s = make_float4(0.f, 0.f, 0.f, 0.f);
    const float4* V1 = (const float4*)g_V1;
    #pragma unroll
    for (int d = -HALF; d <= HALF; d++) {
        int r = row + d;
        if (r >= 0 && r < RES) {
            float4 t = __ldg(V1 + (size_t)r * NQ + c4);
            s.x += t.x; s.y += t.y; s.z += t.z; s.w += t.w;
        }
    }
    float4 B = ((const float4*)g_V0)[i];
    float4 e;
    e.x = (B.x >= 0.f) ? B.x + s.x * INV_AREA : B.x;
    e.y = (B.y >= 0.f) ? B.y + s.y * INV_AREA : B.y;
    e.z = (B.z >= 0.f) ? B.z + s.z * INV_AREA : B.z;
    e.w = (B.w >= 0.f) ? B.w + s.w * INV_AREA : B.w;
    ((float4*)g_E)[i] = e;
}

// ---------------------------------------------------------------------------
// Kernel 3: KFT fused Jacobi steps; V register-resident.
// FROMX: input is raw x; V0 computed inline as (e>=0 ? x : bc).
// ---------------------------------------------------------------------------
template <int KFT, bool FROMX, bool BORDER, int FINAL>
__device__ __forceinline__ void jfuse_body(const float* __restrict__ Vin,
                                           float* __restrict__ Vout,
                                           float* smem) {
    int tx = threadIdx.x & 31;
    int ty = threadIdx.x >> 5;            // 0..15
    int gr0 = blockIdx.y * TY - HY;
    int gc0 = blockIdx.x * TX - HX;
    int cb  = gc0 + tx * 4;
    int r0  = ty * RPT;

    bool is_ledge = BORDER && (cb == 0);
    bool is_redge = BORDER && (cb + 3 == RES - 1);

    // ---- fill: V into regs; E -> (w, a) regs ----
    float4 v[RPT], w[RPT], a[RPT];
    #pragma unroll
    for (int j = 0; j < RPT; j++) {
        int r = r0 + j;
        float4 ev, xv;
        if (!BORDER) {
            size_t off = (size_t)(gr0 + r) * RES + cb;
            xv = *(const float4*)(Vin + off);
            ev = *(const float4*)(g_E + off);
        } else {
            int gr = min(max(gr0 + r, 0), RES - 1);
            size_t rowoff = (size_t)gr * RES;
            if (cb >= 0 && cb + 3 < RES) {
                xv = *(const float4*)(Vin + rowoff + cb);
                ev = *(const float4*)(g_E + rowoff + cb);
            } else {
                int c0i = min(max(cb + 0, 0), RES - 1);
                int c1i = min(max(cb + 1, 0), RES - 1);
                int c2i = min(max(cb + 2, 0), RES - 1);
                int c3i = min(max(cb + 3, 0), RES - 1);
                xv = make_float4(Vin[rowoff + c0i], Vin[rowoff + c1i],
                                 Vin[rowoff + c2i], Vin[rowoff + c3i]);
                ev = make_float4(g_E[rowoff + c0i], g_E[rowoff + c1i],
                                 g_E[rowoff + c2i], g_E[rowoff + c3i]);
            }
        }
        w[j].x = (ev.x >= 0.f) ? 0.25f : 0.f;
        w[j].y = (ev.y >= 0.f) ? 0.25f : 0.f;
        w[j].z = (ev.z >= 0.f) ? 0.25f : 0.f;
        w[j].w = (ev.w >= 0.f) ? 0.25f : 0.f;
        a[j].x = (ev.x >= 0.f) ? ev.x : -ev.x - 1.f;
        a[j].y = (ev.y >= 0.f) ? ev.y : -ev.y - 1.f;
        a[j].z = (ev.z >= 0.f) ? ev.z : -ev.z - 1.f;
        a[j].w = (ev.w >= 0.f) ? ev.w : -ev.w - 1.f;
        if (FROMX) {
            // V0 = interior ? x : bc   (bc == a at boundary cells)
            v[j].x = (ev.x >= 0.f) ? xv.x : a[j].x;
            v[j].y = (ev.y >= 0.f) ? xv.y : a[j].y;
            v[j].z = (ev.z >= 0.f) ? xv.z : a[j].z;
            v[j].w = (ev.w >= 0.f) ? xv.w : a[j].w;
        } else {
            v[j] = xv;
        }
    }

    #pragma unroll
    for (int s = 0; s < KFT; s++) {
        float* top = smem + (s & 1) * (2 * HALO_STRIDE);
        float* bot = top + HALO_STRIDE;
        *(float4*)(top + ty * RX + 4 * tx) = v[0];
        *(float4*)(bot + ty * RX + 4 * tx) = v[RPT - 1];
        __syncthreads();
        float4 above = (ty > 0)       ? *(const float4*)(bot + (ty - 1) * RX + 4 * tx) : v[0];
        float4 below = (ty < NWY - 1) ? *(const float4*)(top + (ty + 1) * RX + 4 * tx) : v[RPT - 1];
        bool last = (s == KFT - 1);
        float4 pm1 = above;
        #pragma unroll
        for (int j = 0; j < RPT; j++) {
            float4 np1 = (j < RPT - 1) ? v[j + 1] : below;
            float4 cur = v[j];
            float4 up = pm1;
            float4 dn = np1;
            if (BORDER) {
                int grr = gr0 + r0 + j;
                if (grr <= 0)       up = cur;
                if (grr >= RES - 1) dn = cur;
            }
            float lf = __shfl_up_sync(0xffffffffu, cur.w, 1);
            float rg = __shfl_down_sync(0xffffffffu, cur.x, 1);
            if (tx == 0 || is_ledge)  lf = cur.x;
            if (tx == 31 || is_redge) rg = cur.w;
            float2 t01 = addx2(make_float2(up.x, up.y), make_float2(dn.x, dn.y));
            float2 t23 = addx2(make_float2(up.z, up.w), make_float2(dn.z, dn.w));
            float h0 = lf    + cur.y;
            float h1 = cur.x + cur.z;
            float h2 = cur.y + cur.w;
            float h3 = cur.z + rg;
            float2 u01 = addx2(t01, make_float2(h0, h1));
            float2 u23 = addx2(t23, make_float2(h2, h3));
            float2 o01 = fmax2(make_float2(w[j].x, w[j].y), u01,
                               make_float2(a[j].x, a[j].y));
            float2 o23 = fmax2(make_float2(w[j].z, w[j].w), u23,
                               make_float2(a[j].z, a[j].w));
            float4 o = make_float4(o01.x, o01.y, o23.x, o23.y);
            if (!last) {
                v[j] = o;
            } else {
                int r = r0 + j;
                if (r >= HY && r < RY - HY && tx >= 2 && tx <= 29) {
                    bool ok = true;
                    if (BORDER) ok = (gr0 + r) < RES && (cb + 3) < RES;
                    if (ok) {
                        if (FINAL) {
                            o.x = (o.x >= 1.f) ? 0.95f : o.x;
                            o.y = (o.y >= 1.f) ? 0.95f : o.y;
                            o.z = (o.z >= 1.f) ? 0.95f : o.z;
                            o.w = (o.w >= 1.f) ? 0.95f : o.w;
                        }
                        *(float4*)(Vout + (size_t)(gr0 + r) * RES + cb) = o;
                    }
                }
            }
            pm1 = cur;
        }
    }
}

template <int KFT, bool FROMX, int FINAL>
__global__ __launch_bounds__(NTHREADS, 2)
void k_jfuse(const float* __restrict__ Vin, float* __restrict__ Vout) {
    __shared__ float smem[2 * 2 * HALO_STRIDE];   // 32 KB
    bool border = (blockIdx.x == 0) | (blockIdx.x == gridDim.x - 1) |
                  (blockIdx.y == 0) | (blockIdx.y == gridDim.y - 1);
    if (!border) jfuse_body<KFT, FROMX, false, FINAL>(Vin, Vout, smem);
    else         jfuse_body<KFT, FROMX, true,  FINAL>(Vin, Vout, smem);
}

// ---------------------------------------------------------------------------
extern "C" void kernel_launch(void* const* d_in, const int* in_sizes, int n_in,
                              void* d_out, int out_size) {
    const float* x  = (const float*)d_in[0];
    const float* bt = (const float*)d_in[1];
    const float* bc = (const float*)d_in[2];
    const float* C  = (const float*)d_in[3];
    float* out  = (float*)d_out;
    float* cpos = out + (size_t)NTOT;

    // fused init + horizontal box sum  (B -> g_V0, hsum -> g_V1)
    {
        dim3 b(256), g(RES / 1024, RES);   // 4 x 4096
        k_init_hbox<<<g, b>>>((const float4*)bt, (const float4*)bc,
                              (const float4*)C, (float4*)cpos, bt, bc);
    }
    // vertical box sum + E build (reads g_V0 + g_V1)
    {
        dim3 b(256, 1), g(NQ / 256, RES);
        k_vbox_combine<<<g, b>>>();
    }
    // 20 Jacobi iters = 3 fused passes (7 + 7 + 6)
    {
        float *dv0, *dv1;
        cudaGetSymbolAddress((void**)&dv0, g_V0);
        cudaGetSymbolAddress((void**)&dv1, g_V1);
        dim3 b(NTHREADS), g((RES + TX - 1) / TX, (RES + TY - 1) / TY);   // 37 x 82
        k_jfuse<7, true,  0><<<g, b>>>(x,   dv1);   // V0 computed inline from x
        k_jfuse<7, false, 0><<<g, b>>>(dv1, dv0);
        k_jfuse<6, false, 1><<<g, b>>>(dv0, out);   // final 6 steps + clamp
    }
}